// round 5
// baseline (speedup 1.0000x reference)
#include <cuda_runtime.h>

// Problem dims (fixed for this dataset)
#define BB   2
#define SS   2048
#define DD   1024
#define HH   16
#define DHD  64
#define MM   (BB*SS)      // 4096 rows
// QKV combined N = 3*1024 = 3072

// Scratch (allocation-free rule: __device__ globals)
__device__ float g_Q[MM*DD];
__device__ float g_K[MM*DD];
__device__ float g_V[MM*DD];
__device__ float g_Z[MM*DD];

// ---------------------------------------------------------------------------
// GEMM 1: QKV projection.  C[m, n] = sum_k x[m,k] * W[n/1024][h,k,d] + bias
// Tile 128x128x16, 256 threads, 8x8 per thread.
// ---------------------------------------------------------------------------
__global__ __launch_bounds__(256) void qkv_gemm(
    const float* __restrict__ x,
    const float* __restrict__ Wq, const float* __restrict__ Wk, const float* __restrict__ Wv,
    const float* __restrict__ bq, const float* __restrict__ bk, const float* __restrict__ bv)
{
    __shared__ __align__(16) float As[16][132];  // A transposed: As[k][m]
    __shared__ __align__(16) float Bs[16][132];  // Bs[k][n]

    const int n0 = blockIdx.x * 128;   // 0..2944
    const int m0 = blockIdx.y * 128;
    const int t  = threadIdx.x;
    const int tr = t >> 4, tc = t & 15;

    const int which = n0 / DD;               // 0=Q,1=K,2=V (tile never spans)
    const float* __restrict__ W    = (which == 0) ? Wq : (which == 1) ? Wk : Wv;
    const float* __restrict__ bias = (which == 0) ? bq : (which == 1) ? bk : bv;
    float* __restrict__ out        = (which == 0) ? g_Q : (which == 1) ? g_K : g_V;
    const int nh = n0 % DD;                  // column base within [0,1024)

    float acc[8][8];
#pragma unroll
    for (int i = 0; i < 8; i++)
#pragma unroll
        for (int j = 0; j < 8; j++) acc[i][j] = 0.0f;

    for (int k0 = 0; k0 < DD; k0 += 16) {
        // Load A tile 128x16 (transposed into As)
#pragma unroll
        for (int l = 0; l < 2; l++) {
            int idx = t + l * 256;            // 0..511
            int row = idx >> 2;               // 0..127
            int kc  = (idx & 3) * 4;          // 0,4,8,12
            float4 v = *(const float4*)&x[(m0 + row) * DD + k0 + kc];
            As[kc + 0][row] = v.x;
            As[kc + 1][row] = v.y;
            As[kc + 2][row] = v.z;
            As[kc + 3][row] = v.w;
        }
        // Load B tile 16x128 from [H, D, Dh] layout
#pragma unroll
        for (int l = 0; l < 2; l++) {
            int idx = t + l * 256;
            int kr  = idx >> 5;               // 0..15
            int nc  = (idx & 31) * 4;         // 0..124
            int n   = nh + nc;
            int h   = n >> 6;
            int d   = n & 63;                 // multiple of 4, <=60
            float4 v = *(const float4*)&W[h * (DD * DHD) + (k0 + kr) * DHD + d];
            *(float4*)&Bs[kr][nc] = v;
        }
        __syncthreads();

#pragma unroll
        for (int k = 0; k < 16; k++) {
            float4 a0 = *(const float4*)&As[k][tr * 8];
            float4 a1 = *(const float4*)&As[k][tr * 8 + 4];
            float4 b0 = *(const float4*)&Bs[k][tc * 8];
            float4 b1 = *(const float4*)&Bs[k][tc * 8 + 4];
            float a[8] = {a0.x, a0.y, a0.z, a0.w, a1.x, a1.y, a1.z, a1.w};
            float b[8] = {b0.x, b0.y, b0.z, b0.w, b1.x, b1.y, b1.z, b1.w};
#pragma unroll
            for (int i = 0; i < 8; i++)
#pragma unroll
                for (int j = 0; j < 8; j++) acc[i][j] += a[i] * b[j];
        }
        __syncthreads();
    }

    // Epilogue: add bias, store
#pragma unroll
    for (int i = 0; i < 8; i++) {
        int m = m0 + tr * 8 + i;
#pragma unroll
        for (int j = 0; j < 8; j += 4) {
            int n = nh + tc * 8 + j;
            float4 v;
            v.x = acc[i][j + 0] + bias[n + 0];
            v.y = acc[i][j + 1] + bias[n + 1];
            v.z = acc[i][j + 2] + bias[n + 2];
            v.w = acc[i][j + 3] + bias[n + 3];
            *(float4*)&out[m * DD + n] = v;
        }
    }
}

// ---------------------------------------------------------------------------
// Flash attention (causal), fp32, 64x64 tiles, 256 threads (16x16),
// each thread owns a 4x4 patch of S and of O.
// Smem strides: Q/K/P = 68 (16B-aligned, conflict-benign), V = 64.
// ---------------------------------------------------------------------------
#define QS_STRIDE 68
#define FLASH_SMEM ((64*QS_STRIDE*2 + 64*64) * (int)sizeof(float))   // 51200 B

__global__ __launch_bounds__(256) void flash_kernel()
{
    extern __shared__ __align__(16) float sm[];
    float* Qs = sm;                       // [64][68]
    float* KP = sm + 64 * QS_STRIDE;      // [64][68]  K tile, then reused for P
    float* Vs = sm + 2 * 64 * QS_STRIDE;  // [64][64]

    const int qt = blockIdx.x;   // q tile 0..31
    const int h  = blockIdx.y;
    const int b  = blockIdx.z;
    const int t  = threadIdx.x;
    const int tr = t >> 4, tc = t & 15;
    const int r0 = tr * 4, c0 = tc * 4;
    const float scale = 0.125f;  // 1/sqrt(64)

    // Load Q tile [64 rows x 64 cols]
    for (int i = t; i < 64 * 16; i += 256) {
        int r  = i >> 4;
        int c4 = (i & 15) * 4;
        float4 v = *(const float4*)&g_Q[(b * SS + qt * 64 + r) * DD + h * 64 + c4];
        *(float4*)&Qs[r * QS_STRIDE + c4] = v;
    }

    float m_i[4], l_i[4], O[4][4];
#pragma unroll
    for (int i = 0; i < 4; i++) {
        m_i[i] = -1e30f; l_i[i] = 0.0f;
#pragma unroll
        for (int j = 0; j < 4; j++) O[i][j] = 0.0f;
    }

    for (int j = 0; j <= qt; j++) {
        __syncthreads();  // prior iter's P/V reads done; Q load done (iter 0)
        // Load K and V tiles (rows j*64 .. j*64+63)
        for (int i = t; i < 64 * 16; i += 256) {
            int r  = i >> 4;
            int c4 = (i & 15) * 4;
            int grow = (b * SS + j * 64 + r) * DD + h * 64 + c4;
            *(float4*)&KP[r * QS_STRIDE + c4] = *(const float4*)&g_K[grow];
            *(float4*)&Vs[r * 64 + c4]        = *(const float4*)&g_V[grow];
        }
        __syncthreads();

        // S = Q K^T  (4x4 per thread), vectorized over d
        float S[4][4];
#pragma unroll
        for (int i = 0; i < 4; i++)
#pragma unroll
            for (int jj = 0; jj < 4; jj++) S[i][jj] = 0.0f;

#pragma unroll
        for (int d4 = 0; d4 < 16; d4++) {
            float4 q[4], kk[4];
#pragma unroll
            for (int i = 0; i < 4; i++) q[i]  = *(const float4*)&Qs[(r0 + i) * QS_STRIDE + d4 * 4];
#pragma unroll
            for (int i = 0; i < 4; i++) kk[i] = *(const float4*)&KP[(c0 + i) * QS_STRIDE + d4 * 4];
#pragma unroll
            for (int i = 0; i < 4; i++)
#pragma unroll
                for (int jj = 0; jj < 4; jj++)
                    S[i][jj] += q[i].x * kk[jj].x + q[i].y * kk[jj].y
                              + q[i].z * kk[jj].z + q[i].w * kk[jj].w;
        }

        // Scale + causal mask (only diagonal tile needs masking)
        if (j == qt) {
#pragma unroll
            for (int i = 0; i < 4; i++)
#pragma unroll
                for (int jj = 0; jj < 4; jj++)
                    S[i][jj] = (c0 + jj <= r0 + i) ? S[i][jj] * scale : -1e30f;
        } else {
#pragma unroll
            for (int i = 0; i < 4; i++)
#pragma unroll
                for (int jj = 0; jj < 4; jj++) S[i][jj] *= scale;
        }

        // Row max over 16 threads sharing a row (xor 8,4,2,1 stays in 16-group)
        float rmax[4];
#pragma unroll
        for (int i = 0; i < 4; i++)
            rmax[i] = fmaxf(fmaxf(S[i][0], S[i][1]), fmaxf(S[i][2], S[i][3]));
#pragma unroll
        for (int o = 8; o >= 1; o >>= 1)
#pragma unroll
            for (int i = 0; i < 4; i++)
                rmax[i] = fmaxf(rmax[i], __shfl_xor_sync(0xffffffffu, rmax[i], o));

        float mnew[4], corr[4];
#pragma unroll
        for (int i = 0; i < 4; i++) {
            mnew[i] = fmaxf(m_i[i], rmax[i]);
            corr[i] = __expf(m_i[i] - mnew[i]);
            m_i[i]  = mnew[i];
        }

        __syncthreads();  // all K reads done before overwriting KP with P

        float rsum[4] = {0.f, 0.f, 0.f, 0.f};
#pragma unroll
        for (int i = 0; i < 4; i++) {
#pragma unroll
            for (int jj = 0; jj < 4; jj++) {
                float p = __expf(S[i][jj] - mnew[i]);
                S[i][jj] = p;
                rsum[i] += p;
            }
            *(float4*)&KP[(r0 + i) * QS_STRIDE + c0] =
                make_float4(S[i][0], S[i][1], S[i][2], S[i][3]);
        }
#pragma unroll
        for (int o = 8; o >= 1; o >>= 1)
#pragma unroll
            for (int i = 0; i < 4; i++)
                rsum[i] += __shfl_xor_sync(0xffffffffu, rsum[i], o);

#pragma unroll
        for (int i = 0; i < 4; i++) {
            l_i[i] = l_i[i] * corr[i] + rsum[i];
#pragma unroll
            for (int jj = 0; jj < 4; jj++) O[i][jj] *= corr[i];
        }
        __syncthreads();  // P visible to all

        // O += P @ V, vectorized over c
#pragma unroll
        for (int c4 = 0; c4 < 16; c4++) {
            float4 pv[4];
#pragma unroll
            for (int i = 0; i < 4; i++)
                pv[i] = *(const float4*)&KP[(r0 + i) * QS_STRIDE + c4 * 4];
            float pm[4][4];
#pragma unroll
            for (int i = 0; i < 4; i++) {
                pm[i][0] = pv[i].x; pm[i][1] = pv[i].y;
                pm[i][2] = pv[i].z; pm[i][3] = pv[i].w;
            }
#pragma unroll
            for (int cc = 0; cc < 4; cc++) {
                float4 v = *(const float4*)&Vs[(c4 * 4 + cc) * 64 + c0];
#pragma unroll
                for (int i = 0; i < 4; i++) {
                    O[i][0] += pm[i][cc] * v.x;
                    O[i][1] += pm[i][cc] * v.y;
                    O[i][2] += pm[i][cc] * v.z;
                    O[i][3] += pm[i][cc] * v.w;
                }
            }
        }
    }

    // Epilogue: normalize, write Z
#pragma unroll
    for (int i = 0; i < 4; i++) {
        float inv = 1.0f / l_i[i];
        float4 v = make_float4(O[i][0] * inv, O[i][1] * inv, O[i][2] * inv, O[i][3] * inv);
        *(float4*)&g_Z[(b * SS + qt * 64 + r0 + i) * DD + h * 64 + c0] = v;
    }
}

// ---------------------------------------------------------------------------
// GEMM 2: output projection. W_O [H,Dh,D] flattens to row-major [1024,1024].
// out[m, n] = sum_k Z[m,k] * Wo[k,n] + sum_h b_O[h,n]
// ---------------------------------------------------------------------------
__global__ __launch_bounds__(256) void out_gemm(
    const float* __restrict__ Wo, const float* __restrict__ bo,
    float* __restrict__ out)
{
    __shared__ __align__(16) float As[16][132];
    __shared__ __align__(16) float Bs[16][132];
    __shared__ float bsum[128];

    const int n0 = blockIdx.x * 128;
    const int m0 = blockIdx.y * 128;
    const int t  = threadIdx.x;
    const int tr = t >> 4, tc = t & 15;

    if (t < 128) {
        float s = 0.0f;
#pragma unroll
        for (int h = 0; h < HH; h++) s += bo[h * DD + n0 + t];
        bsum[t] = s;
    }

    float acc[8][8];
#pragma unroll
    for (int i = 0; i < 8; i++)
#pragma unroll
        for (int j = 0; j < 8; j++) acc[i][j] = 0.0f;

    for (int k0 = 0; k0 < DD; k0 += 16) {
#pragma unroll
        for (int l = 0; l < 2; l++) {
            int idx = t + l * 256;
            int row = idx >> 2;
            int kc  = (idx & 3) * 4;
            float4 v = *(const float4*)&g_Z[(m0 + row) * DD + k0 + kc];
            As[kc + 0][row] = v.x;
            As[kc + 1][row] = v.y;
            As[kc + 2][row] = v.z;
            As[kc + 3][row] = v.w;
        }
#pragma unroll
        for (int l = 0; l < 2; l++) {
            int idx = t + l * 256;
            int kr  = idx >> 5;
            int nc  = (idx & 31) * 4;
            *(float4*)&Bs[kr][nc] = *(const float4*)&Wo[(k0 + kr) * DD + n0 + nc];
        }
        __syncthreads();

#pragma unroll
        for (int k = 0; k < 16; k++) {
            float4 a0 = *(const float4*)&As[k][tr * 8];
            float4 a1 = *(const float4*)&As[k][tr * 8 + 4];
            float4 b0 = *(const float4*)&Bs[k][tc * 8];
            float4 b1 = *(const float4*)&Bs[k][tc * 8 + 4];
            float a[8] = {a0.x, a0.y, a0.z, a0.w, a1.x, a1.y, a1.z, a1.w};
            float b[8] = {b0.x, b0.y, b0.z, b0.w, b1.x, b1.y, b1.z, b1.w};
#pragma unroll
            for (int i = 0; i < 8; i++)
#pragma unroll
                for (int j = 0; j < 8; j++) acc[i][j] += a[i] * b[j];
        }
        __syncthreads();
    }

#pragma unroll
    for (int i = 0; i < 8; i++) {
        int m = m0 + tr * 8 + i;
#pragma unroll
        for (int j = 0; j < 8; j += 4) {
            int nc = tc * 8 + j;
            float4 v;
            v.x = acc[i][j + 0] + bsum[nc + 0];
            v.y = acc[i][j + 1] + bsum[nc + 1];
            v.z = acc[i][j + 2] + bsum[nc + 2];
            v.w = acc[i][j + 3] + bsum[nc + 3];
            *(float4*)&out[m * DD + n0 + nc] = v;
        }
    }
}

// ---------------------------------------------------------------------------
extern "C" void kernel_launch(void* const* d_in, const int* in_sizes, int n_in,
                              void* d_out, int out_size)
{
    (void)in_sizes; (void)n_in; (void)out_size;
    const float* x  = (const float*)d_in[0];
    const float* Wq = (const float*)d_in[1];
    const float* bq = (const float*)d_in[2];
    const float* Wk = (const float*)d_in[3];
    const float* bk = (const float*)d_in[4];
    const float* Wv = (const float*)d_in[5];
    const float* Wo = (const float*)d_in[6];
    const float* bv = (const float*)d_in[7];
    const float* bo = (const float*)d_in[8];
    float* out = (float*)d_out;

    cudaFuncSetAttribute(flash_kernel,
                         cudaFuncAttributeMaxDynamicSharedMemorySize, FLASH_SMEM);

    qkv_gemm<<<dim3(24, 32), 256>>>(x, Wq, Wk, Wv, bq, bk, bv);
    flash_kernel<<<dim3(32, HH, BB), 256, FLASH_SMEM>>>();
    out_gemm<<<dim3(8, 32), 256>>>(Wo, bo, out);
}

// round 6
// speedup vs baseline: 1.7761x; 1.7761x over previous
#include <cuda_runtime.h>
#include <cstdint>

// Problem dims (fixed for this dataset)
#define BB   2
#define SS   2048
#define DD   1024
#define HH   16
#define DHD  64
#define MM   (BB*SS)      // 4096 rows

// Scratch (allocation-free rule: __device__ globals)
__device__ float g_Q[MM*DD];
__device__ float g_K[MM*DD];
__device__ float g_V[MM*DD];
__device__ float g_Z[MM*DD];

// ---------------------------------------------------------------------------
// tf32 helpers
// ---------------------------------------------------------------------------
__device__ __forceinline__ uint32_t f2tf(float v) {
    uint32_t r; asm("cvt.rna.tf32.f32 %0, %1;" : "=r"(r) : "f"(v)); return r;
}
__device__ __forceinline__ void split_tf(float v, uint32_t &hi, uint32_t &lo) {
    hi = f2tf(v);
    lo = f2tf(v - __uint_as_float(hi));
}
// D += A(16x8) * B(8x8), tf32 inputs, f32 accum.
__device__ __forceinline__ void mma_tf32(float* d, const uint32_t* a, const uint32_t* b) {
    asm volatile(
        "mma.sync.aligned.m16n8k8.row.col.f32.tf32.tf32.f32 "
        "{%0,%1,%2,%3}, {%4,%5,%6,%7}, {%8,%9}, {%0,%1,%2,%3};\n"
        : "+f"(d[0]), "+f"(d[1]), "+f"(d[2]), "+f"(d[3])
        : "r"(a[0]), "r"(a[1]), "r"(a[2]), "r"(a[3]), "r"(b[0]), "r"(b[1]));
}

// ---------------------------------------------------------------------------
// GEMM 1: QKV projection with hi/lo tf32 split (3-pass) for fp32-level accuracy.
// Block tile 128x128x16, 8 warps, each warp 64x32 (4 m16-tiles x 4 n8-tiles).
// Smem: A [m][20] (frag banks distinct), B [k][136] (frag banks distinct).
// ---------------------------------------------------------------------------
#define ASTR 20
#define BSTR 136

__global__ __launch_bounds__(256) void qkv_gemm(
    const float* __restrict__ x,
    const float* __restrict__ Wq, const float* __restrict__ Wk, const float* __restrict__ Wv,
    const float* __restrict__ bq, const float* __restrict__ bk, const float* __restrict__ bv)
{
    __shared__ __align__(16) uint32_t Ah[128][ASTR], Al[128][ASTR];
    __shared__ __align__(16) uint32_t Bh[16][BSTR],  Bl[16][BSTR];

    const int n0   = blockIdx.x * 128;   // 0..2944
    const int m0   = blockIdx.y * 128;
    const int t    = threadIdx.x;
    const int lane = t & 31, w = t >> 5;
    const int g    = lane >> 2, tq = lane & 3;
    const int wm   = w & 1,  wn = w >> 1;   // warp grid 2 x 4

    const int which = n0 / DD;           // 0=Q,1=K,2=V (tile never spans)
    const float* __restrict__ W    = (which == 0) ? Wq : (which == 1) ? Wk : Wv;
    const float* __restrict__ bias = (which == 0) ? bq : (which == 1) ? bk : bv;
    float* __restrict__ out        = (which == 0) ? g_Q : (which == 1) ? g_K : g_V;
    const int nh = n0 % DD;

    float acc[4][4][4];
#pragma unroll
    for (int mt = 0; mt < 4; mt++)
#pragma unroll
        for (int nt = 0; nt < 4; nt++)
#pragma unroll
            for (int i = 0; i < 4; i++) acc[mt][nt][i] = 0.0f;

    for (int k0 = 0; k0 < DD; k0 += 16) {
        // ---- load + split A tile (128 x 16) ----
#pragma unroll
        for (int l = 0; l < 2; l++) {
            int idx = t + l * 256;            // 0..511
            int row = idx >> 2;               // 0..127
            int kc  = (idx & 3) * 4;          // 0,4,8,12
            float4 v = *(const float4*)&x[(m0 + row) * DD + k0 + kc];
            uint32_t h0,l0,h1,l1,h2,l2,h3,l3;
            split_tf(v.x,h0,l0); split_tf(v.y,h1,l1);
            split_tf(v.z,h2,l2); split_tf(v.w,h3,l3);
            *(uint4*)&Ah[row][kc] = make_uint4(h0,h1,h2,h3);
            *(uint4*)&Al[row][kc] = make_uint4(l0,l1,l2,l3);
        }
        // ---- load + split B tile (16 x 128) from [H, D, Dh] ----
#pragma unroll
        for (int l = 0; l < 2; l++) {
            int idx = t + l * 256;
            int kr  = idx >> 5;               // 0..15
            int nc  = (idx & 31) * 4;         // 0..124
            int n   = nh + nc;
            int hh  = n >> 6;
            int d   = n & 63;
            float4 v = *(const float4*)&W[hh * (DD * DHD) + (k0 + kr) * DHD + d];
            uint32_t h0,l0,h1,l1,h2,l2,h3,l3;
            split_tf(v.x,h0,l0); split_tf(v.y,h1,l1);
            split_tf(v.z,h2,l2); split_tf(v.w,h3,l3);
            *(uint4*)&Bh[kr][nc] = make_uint4(h0,h1,h2,h3);
            *(uint4*)&Bl[kr][nc] = make_uint4(l0,l1,l2,l3);
        }
        __syncthreads();

#pragma unroll
        for (int kk = 0; kk < 16; kk += 8) {
            uint32_t ah[4][4], al[4][4], bh[4][2], bl[4][2];
#pragma unroll
            for (int mt = 0; mt < 4; mt++) {
                int mr = wm * 64 + mt * 16 + g;
                ah[mt][0] = Ah[mr][kk + tq];       ah[mt][1] = Ah[mr + 8][kk + tq];
                ah[mt][2] = Ah[mr][kk + tq + 4];   ah[mt][3] = Ah[mr + 8][kk + tq + 4];
                al[mt][0] = Al[mr][kk + tq];       al[mt][1] = Al[mr + 8][kk + tq];
                al[mt][2] = Al[mr][kk + tq + 4];   al[mt][3] = Al[mr + 8][kk + tq + 4];
            }
#pragma unroll
            for (int nt = 0; nt < 4; nt++) {
                int nb = wn * 32 + nt * 8 + g;
                bh[nt][0] = Bh[kk + tq][nb];  bh[nt][1] = Bh[kk + tq + 4][nb];
                bl[nt][0] = Bl[kk + tq][nb];  bl[nt][1] = Bl[kk + tq + 4][nb];
            }
#pragma unroll
            for (int mt = 0; mt < 4; mt++)
#pragma unroll
                for (int nt = 0; nt < 4; nt++) mma_tf32(acc[mt][nt], ah[mt], bh[nt]);
#pragma unroll
            for (int mt = 0; mt < 4; mt++)
#pragma unroll
                for (int nt = 0; nt < 4; nt++) mma_tf32(acc[mt][nt], ah[mt], bl[nt]);
#pragma unroll
            for (int mt = 0; mt < 4; mt++)
#pragma unroll
                for (int nt = 0; nt < 4; nt++) mma_tf32(acc[mt][nt], al[mt], bh[nt]);
        }
        __syncthreads();
    }

    // Epilogue: bias + store (accum layout: rows g,g+8; cols 2tq,2tq+1)
#pragma unroll
    for (int mt = 0; mt < 4; mt++) {
        int m = m0 + wm * 64 + mt * 16 + g;
#pragma unroll
        for (int nt = 0; nt < 4; nt++) {
            int n = nh + wn * 32 + nt * 8 + 2 * tq;
            float b0 = bias[n], b1 = bias[n + 1];
            float2 v0 = make_float2(acc[mt][nt][0] + b0, acc[mt][nt][1] + b1);
            float2 v1 = make_float2(acc[mt][nt][2] + b0, acc[mt][nt][3] + b1);
            *(float2*)&out[m * DD + n]       = v0;
            *(float2*)&out[(m + 8) * DD + n] = v1;
        }
    }
}

// ---------------------------------------------------------------------------
// Flash attention (causal), tf32 mma. 64x64 tiles, 4 warps (128 thr).
// Warp w owns q-rows [w*16, w*16+16): S warp tile 16x64, O warp tile 16x64.
// Q fragments live in registers for the whole j-loop. P round-trips through
// warp-private smem (Q staging region reused).
// ---------------------------------------------------------------------------
#define KSTR 68   // Ks / Ps stride (frag banks 4g+t distinct)
#define VSTR 72   // Vs stride     (frag banks 8t+g distinct)
#define FLASH_SMEM ((64*KSTR + 64*VSTR + 64*KSTR) * 4)   // 53248 B

__global__ __launch_bounds__(128) void flash_kernel()
{
    extern __shared__ __align__(16) uint32_t sm[];
    uint32_t* Ks = sm;                          // [64][68]
    uint32_t* Vs = sm + 64 * KSTR;              // [64][72]
    uint32_t* Ps = sm + 64 * KSTR + 64 * VSTR;  // [64][68] (Q staging, then P)

    const int qt = blockIdx.x, h = blockIdx.y, b = blockIdx.z;
    const int t = threadIdx.x, lane = t & 31, w = t >> 5;
    const int g = lane >> 2, tq = lane & 3;
    const float scale = 0.125f;  // 1/sqrt(64)

    // Load this warp's Q rows into Ps region (tf32), then frags to registers.
#pragma unroll
    for (int i = 0; i < 8; i++) {
        int idx = lane + i * 32;          // 0..255
        int r   = idx >> 4;               // 0..15
        int c4  = (idx & 15) * 4;
        float4 v = *(const float4*)&g_Q[(b * SS + qt * 64 + w * 16 + r) * DD + h * 64 + c4];
        *(uint4*)&Ps[(w * 16 + r) * KSTR + c4] =
            make_uint4(f2tf(v.x), f2tf(v.y), f2tf(v.z), f2tf(v.w));
    }
    __syncwarp();
    uint32_t qa[8][4];
#pragma unroll
    for (int kk = 0; kk < 8; kk++) {
        int rb = (w * 16 + g) * KSTR;
        qa[kk][0] = Ps[rb + kk * 8 + tq];
        qa[kk][1] = Ps[rb + 8 * KSTR + kk * 8 + tq];
        qa[kk][2] = Ps[rb + kk * 8 + tq + 4];
        qa[kk][3] = Ps[rb + 8 * KSTR + kk * 8 + tq + 4];
    }

    float m_i[2] = {-1e30f, -1e30f}, l_i[2] = {0.0f, 0.0f};
    float O[8][4];
#pragma unroll
    for (int nt = 0; nt < 8; nt++)
#pragma unroll
        for (int i = 0; i < 4; i++) O[nt][i] = 0.0f;

    for (int j = 0; j <= qt; j++) {
        __syncthreads();   // prior iter's Ks/Vs reads complete
        // ---- load K,V tiles (tf32) ----
#pragma unroll
        for (int i = 0; i < 8; i++) {
            int idx = t + i * 128;        // 0..1023
            int r   = idx >> 4;           // 0..63
            int c4  = (idx & 15) * 4;
            int go  = (b * SS + j * 64 + r) * DD + h * 64 + c4;
            float4 kv = *(const float4*)&g_K[go];
            float4 vv = *(const float4*)&g_V[go];
            *(uint4*)&Ks[r * KSTR + c4] = make_uint4(f2tf(kv.x), f2tf(kv.y), f2tf(kv.z), f2tf(kv.w));
            *(uint4*)&Vs[r * VSTR + c4] = make_uint4(f2tf(vv.x), f2tf(vv.y), f2tf(vv.z), f2tf(vv.w));
        }
        __syncthreads();

        // ---- S = Q K^T ----
        float S[8][4];
#pragma unroll
        for (int nt = 0; nt < 8; nt++)
#pragma unroll
            for (int i = 0; i < 4; i++) S[nt][i] = 0.0f;

#pragma unroll
        for (int kk = 0; kk < 8; kk++) {
#pragma unroll
            for (int nt = 0; nt < 8; nt++) {
                uint32_t kb[2];
                kb[0] = Ks[(nt * 8 + g) * KSTR + kk * 8 + tq];
                kb[1] = Ks[(nt * 8 + g) * KSTR + kk * 8 + tq + 4];
                mma_tf32(S[nt], qa[kk], kb);
            }
        }

        // ---- scale + causal mask ----
        if (j == qt) {
            int r0 = w * 16 + g, r1 = r0 + 8;
#pragma unroll
            for (int nt = 0; nt < 8; nt++) {
                int c = nt * 8 + 2 * tq;
                S[nt][0] = (c     <= r0) ? S[nt][0] * scale : -1e30f;
                S[nt][1] = (c + 1 <= r0) ? S[nt][1] * scale : -1e30f;
                S[nt][2] = (c     <= r1) ? S[nt][2] * scale : -1e30f;
                S[nt][3] = (c + 1 <= r1) ? S[nt][3] * scale : -1e30f;
            }
        } else {
#pragma unroll
            for (int nt = 0; nt < 8; nt++)
#pragma unroll
                for (int i = 0; i < 4; i++) S[nt][i] *= scale;
        }

        // ---- online softmax (rows g and g+8; 4-lane quads share a row) ----
        float mx0 = -1e30f, mx1 = -1e30f;
#pragma unroll
        for (int nt = 0; nt < 8; nt++) {
            mx0 = fmaxf(mx0, fmaxf(S[nt][0], S[nt][1]));
            mx1 = fmaxf(mx1, fmaxf(S[nt][2], S[nt][3]));
        }
        mx0 = fmaxf(mx0, __shfl_xor_sync(0xffffffffu, mx0, 1));
        mx0 = fmaxf(mx0, __shfl_xor_sync(0xffffffffu, mx0, 2));
        mx1 = fmaxf(mx1, __shfl_xor_sync(0xffffffffu, mx1, 1));
        mx1 = fmaxf(mx1, __shfl_xor_sync(0xffffffffu, mx1, 2));

        float mn0 = fmaxf(m_i[0], mx0), mn1 = fmaxf(m_i[1], mx1);
        float c0 = __expf(m_i[0] - mn0), c1 = __expf(m_i[1] - mn1);
        m_i[0] = mn0; m_i[1] = mn1;

        float rs0 = 0.0f, rs1 = 0.0f;
#pragma unroll
        for (int nt = 0; nt < 8; nt++) {
            float p0 = __expf(S[nt][0] - mn0);
            float p1 = __expf(S[nt][1] - mn0);
            float p2 = __expf(S[nt][2] - mn1);
            float p3 = __expf(S[nt][3] - mn1);
            rs0 += p0 + p1; rs1 += p2 + p3;
            int cb = nt * 8 + 2 * tq;
            *(uint2*)&Ps[(w * 16 + g) * KSTR + cb]     = make_uint2(f2tf(p0), f2tf(p1));
            *(uint2*)&Ps[(w * 16 + g + 8) * KSTR + cb] = make_uint2(f2tf(p2), f2tf(p3));
        }
        rs0 += __shfl_xor_sync(0xffffffffu, rs0, 1);
        rs0 += __shfl_xor_sync(0xffffffffu, rs0, 2);
        rs1 += __shfl_xor_sync(0xffffffffu, rs1, 1);
        rs1 += __shfl_xor_sync(0xffffffffu, rs1, 2);

        l_i[0] = l_i[0] * c0 + rs0;
        l_i[1] = l_i[1] * c1 + rs1;
#pragma unroll
        for (int nt = 0; nt < 8; nt++) {
            O[nt][0] *= c0; O[nt][1] *= c0;
            O[nt][2] *= c1; O[nt][3] *= c1;
        }
        __syncwarp();   // P visible within warp (Ps region is warp-private)

        // ---- O += P V ----
#pragma unroll
        for (int kk = 0; kk < 8; kk++) {
            uint32_t pa[4];
            int rb = (w * 16 + g) * KSTR + kk * 8;
            pa[0] = Ps[rb + tq];
            pa[1] = Ps[rb + 8 * KSTR + tq];
            pa[2] = Ps[rb + tq + 4];
            pa[3] = Ps[rb + 8 * KSTR + tq + 4];
#pragma unroll
            for (int nt = 0; nt < 8; nt++) {
                uint32_t vb[2];
                vb[0] = Vs[(kk * 8 + tq) * VSTR + nt * 8 + g];
                vb[1] = Vs[(kk * 8 + tq + 4) * VSTR + nt * 8 + g];
                mma_tf32(O[nt], pa, vb);
            }
        }
    }

    // Epilogue: normalize, write Z (fp32)
    float inv0 = 1.0f / l_i[0], inv1 = 1.0f / l_i[1];
    int m = b * SS + qt * 64 + w * 16 + g;
#pragma unroll
    for (int nt = 0; nt < 8; nt++) {
        int c = h * 64 + nt * 8 + 2 * tq;
        *(float2*)&g_Z[m * DD + c]       = make_float2(O[nt][0] * inv0, O[nt][1] * inv0);
        *(float2*)&g_Z[(m + 8) * DD + c] = make_float2(O[nt][2] * inv1, O[nt][3] * inv1);
    }
}

// ---------------------------------------------------------------------------
// GEMM 2: output projection, hi/lo tf32 split (3-pass).
// W_O [H,Dh,D] flattens to row-major [1024,1024] with k = h*64+d, matching
// g_Z's column layout. out[m,n] = sum_k Z[m,k]*Wo[k,n] + sum_h b_O[h,n].
// ---------------------------------------------------------------------------
__global__ __launch_bounds__(256) void out_gemm(
    const float* __restrict__ Wo, const float* __restrict__ bo,
    float* __restrict__ out)
{
    __shared__ __align__(16) uint32_t Ah[128][ASTR], Al[128][ASTR];
    __shared__ __align__(16) uint32_t Bh[16][BSTR],  Bl[16][BSTR];
    __shared__ float bsum[128];

    const int n0   = blockIdx.x * 128;
    const int m0   = blockIdx.y * 128;
    const int t    = threadIdx.x;
    const int lane = t & 31, w = t >> 5;
    const int g    = lane >> 2, tq = lane & 3;
    const int wm   = w & 1,  wn = w >> 1;

    if (t < 128) {
        float s = 0.0f;
#pragma unroll
        for (int hh = 0; hh < HH; hh++) s += bo[hh * DD + n0 + t];
        bsum[t] = s;
    }

    float acc[4][4][4];
#pragma unroll
    for (int mt = 0; mt < 4; mt++)
#pragma unroll
        for (int nt = 0; nt < 4; nt++)
#pragma unroll
            for (int i = 0; i < 4; i++) acc[mt][nt][i] = 0.0f;

    for (int k0 = 0; k0 < DD; k0 += 16) {
#pragma unroll
        for (int l = 0; l < 2; l++) {
            int idx = t + l * 256;
            int row = idx >> 2;
            int kc  = (idx & 3) * 4;
            float4 v = *(const float4*)&g_Z[(m0 + row) * DD + k0 + kc];
            uint32_t h0,l0,h1,l1,h2,l2,h3,l3;
            split_tf(v.x,h0,l0); split_tf(v.y,h1,l1);
            split_tf(v.z,h2,l2); split_tf(v.w,h3,l3);
            *(uint4*)&Ah[row][kc] = make_uint4(h0,h1,h2,h3);
            *(uint4*)&Al[row][kc] = make_uint4(l0,l1,l2,l3);
        }
#pragma unroll
        for (int l = 0; l < 2; l++) {
            int idx = t + l * 256;
            int kr  = idx >> 5;
            int nc  = (idx & 31) * 4;
            float4 v = *(const float4*)&Wo[(k0 + kr) * DD + n0 + nc];
            uint32_t h0,l0,h1,l1,h2,l2,h3,l3;
            split_tf(v.x,h0,l0); split_tf(v.y,h1,l1);
            split_tf(v.z,h2,l2); split_tf(v.w,h3,l3);
            *(uint4*)&Bh[kr][nc] = make_uint4(h0,h1,h2,h3);
            *(uint4*)&Bl[kr][nc] = make_uint4(l0,l1,l2,l3);
        }
        __syncthreads();

#pragma unroll
        for (int kk = 0; kk < 16; kk += 8) {
            uint32_t ah[4][4], al[4][4], bh[4][2], bl[4][2];
#pragma unroll
            for (int mt = 0; mt < 4; mt++) {
                int mr = wm * 64 + mt * 16 + g;
                ah[mt][0] = Ah[mr][kk + tq];       ah[mt][1] = Ah[mr + 8][kk + tq];
                ah[mt][2] = Ah[mr][kk + tq + 4];   ah[mt][3] = Ah[mr + 8][kk + tq + 4];
                al[mt][0] = Al[mr][kk + tq];       al[mt][1] = Al[mr + 8][kk + tq];
                al[mt][2] = Al[mr][kk + tq + 4];   al[mt][3] = Al[mr + 8][kk + tq + 4];
            }
#pragma unroll
            for (int nt = 0; nt < 4; nt++) {
                int nb = wn * 32 + nt * 8 + g;
                bh[nt][0] = Bh[kk + tq][nb];  bh[nt][1] = Bh[kk + tq + 4][nb];
                bl[nt][0] = Bl[kk + tq][nb];  bl[nt][1] = Bl[kk + tq + 4][nb];
            }
#pragma unroll
            for (int mt = 0; mt < 4; mt++)
#pragma unroll
                for (int nt = 0; nt < 4; nt++) mma_tf32(acc[mt][nt], ah[mt], bh[nt]);
#pragma unroll
            for (int mt = 0; mt < 4; mt++)
#pragma unroll
                for (int nt = 0; nt < 4; nt++) mma_tf32(acc[mt][nt], ah[mt], bl[nt]);
#pragma unroll
            for (int mt = 0; mt < 4; mt++)
#pragma unroll
                for (int nt = 0; nt < 4; nt++) mma_tf32(acc[mt][nt], al[mt], bh[nt]);
        }
        __syncthreads();
    }

#pragma unroll
    for (int mt = 0; mt < 4; mt++) {
        int m = m0 + wm * 64 + mt * 16 + g;
#pragma unroll
        for (int nt = 0; nt < 4; nt++) {
            int nn = wn * 32 + nt * 8 + 2 * tq;
            float b0 = bsum[nn], b1 = bsum[nn + 1];
            float2 v0 = make_float2(acc[mt][nt][0] + b0, acc[mt][nt][1] + b1);
            float2 v1 = make_float2(acc[mt][nt][2] + b0, acc[mt][nt][3] + b1);
            *(float2*)&out[m * DD + n0 + nn]       = v0;
            *(float2*)&out[(m + 8) * DD + n0 + nn] = v1;
        }
    }
}

// ---------------------------------------------------------------------------
extern "C" void kernel_launch(void* const* d_in, const int* in_sizes, int n_in,
                              void* d_out, int out_size)
{
    (void)in_sizes; (void)n_in; (void)out_size;
    const float* x  = (const float*)d_in[0];
    const float* Wq = (const float*)d_in[1];
    const float* bq = (const float*)d_in[2];
    const float* Wk = (const float*)d_in[3];
    const float* bk = (const float*)d_in[4];
    const float* Wv = (const float*)d_in[5];
    const float* Wo = (const float*)d_in[6];
    const float* bv = (const float*)d_in[7];
    const float* bo = (const float*)d_in[8];
    float* out = (float*)d_out;

    cudaFuncSetAttribute(flash_kernel,
                         cudaFuncAttributeMaxDynamicSharedMemorySize, FLASH_SMEM);

    qkv_gemm<<<dim3(24, 32), 256>>>(x, Wq, Wk, Wv, bq, bk, bv);
    flash_kernel<<<dim3(32, HH, BB), 128, FLASH_SMEM>>>();
    out_gemm<<<dim3(8, 32), 256>>>(Wo, bo, out);
}

// round 7
// speedup vs baseline: 3.2662x; 1.8390x over previous
#include <cuda_runtime.h>
#include <cuda_bf16.h>
#include <cstdint>

// Problem dims (fixed for this dataset)
#define BB   2
#define SS   2048
#define DD   1024
#define HH   16
#define DHD  64
#define MM   (BB*SS)      // 4096 rows
#define NQKV 3072

// Scratch (allocation-free rule: __device__ globals)
__device__ float          g_QKV[MM*NQKV];     // fused Q|K|V, row stride 3072
__device__ float          g_Z[MM*DD];
__device__ __nv_bfloat16  g_Xh[MM*DD],  g_Xl[MM*DD];
__device__ __nv_bfloat16  g_Zh[MM*DD],  g_Zl[MM*DD];
__device__ __nv_bfloat16  g_Wth[NQKV*DD], g_Wtl[NQKV*DD];   // W_qkv^T [n][k]
__device__ __nv_bfloat16  g_Woth[DD*DD],  g_Wotl[DD*DD];    // W_O^T   [n][k]
__device__ float          g_bias[NQKV + DD];

// ---------------------------------------------------------------------------
// helpers
// ---------------------------------------------------------------------------
__device__ __forceinline__ void bsplit(float v, __nv_bfloat16 &h, __nv_bfloat16 &l) {
    h = __float2bfloat16_rn(v);
    l = __float2bfloat16_rn(v - __bfloat162float(h));
}
__device__ __forceinline__ uint32_t f2tf(float v) {
    uint32_t r; asm("cvt.rna.tf32.f32 %0, %1;" : "=r"(r) : "f"(v)); return r;
}
__device__ __forceinline__ void mma_tf32(float* d, const uint32_t* a, const uint32_t* b) {
    asm volatile(
        "mma.sync.aligned.m16n8k8.row.col.f32.tf32.tf32.f32 "
        "{%0,%1,%2,%3}, {%4,%5,%6,%7}, {%8,%9}, {%0,%1,%2,%3};\n"
        : "+f"(d[0]), "+f"(d[1]), "+f"(d[2]), "+f"(d[3])
        : "r"(a[0]), "r"(a[1]), "r"(a[2]), "r"(a[3]), "r"(b[0]), "r"(b[1]));
}
__device__ __forceinline__ void mma_bf16(float* d, const uint32_t* a, const uint32_t* b) {
    asm volatile(
        "mma.sync.aligned.m16n8k16.row.col.f32.bf16.bf16.f32 "
        "{%0,%1,%2,%3}, {%4,%5,%6,%7}, {%8,%9}, {%0,%1,%2,%3};\n"
        : "+f"(d[0]), "+f"(d[1]), "+f"(d[2]), "+f"(d[3])
        : "r"(a[0]), "r"(a[1]), "r"(a[2]), "r"(a[3]), "r"(b[0]), "r"(b[1]));
}
__device__ __forceinline__ void ldm4(uint32_t* r, uint32_t addr) {
    asm volatile("ldmatrix.sync.aligned.m8n8.x4.shared.b16 {%0,%1,%2,%3}, [%4];"
                 : "=r"(r[0]), "=r"(r[1]), "=r"(r[2]), "=r"(r[3]) : "r"(addr));
}
__device__ __forceinline__ uint32_t smem_u32(const void* p) {
    uint32_t a;
    asm("{ .reg .u64 t; cvta.to.shared.u64 t, %1; cvt.u32.u64 %0, t; }" : "=r"(a) : "l"(p));
    return a;
}

// ---------------------------------------------------------------------------
// Pre-pass kernels: split to bf16 hi/lo (and transpose for weights)
// ---------------------------------------------------------------------------
__global__ __launch_bounds__(256) void split_ext(const float* __restrict__ in,
                                                 __nv_bfloat16* __restrict__ oh,
                                                 __nv_bfloat16* __restrict__ ol)
{
    int i = (blockIdx.x * 256 + threadIdx.x) * 4;
    float4 v = *(const float4*)&in[i];
    __nv_bfloat16 h0,l0,h1,l1,h2,l2,h3,l3;
    bsplit(v.x,h0,l0); bsplit(v.y,h1,l1); bsplit(v.z,h2,l2); bsplit(v.w,h3,l3);
    *(__nv_bfloat162*)&oh[i]     = __nv_bfloat162(h0,h1);
    *(__nv_bfloat162*)&oh[i + 2] = __nv_bfloat162(h2,h3);
    *(__nv_bfloat162*)&ol[i]     = __nv_bfloat162(l0,l1);
    *(__nv_bfloat162*)&ol[i + 2] = __nv_bfloat162(l2,l3);
}

__global__ __launch_bounds__(256) void split_z()
{
    int i = (blockIdx.x * 256 + threadIdx.x) * 4;
    float4 v = *(const float4*)&g_Z[i];
    __nv_bfloat16 h0,l0,h1,l1,h2,l2,h3,l3;
    bsplit(v.x,h0,l0); bsplit(v.y,h1,l1); bsplit(v.z,h2,l2); bsplit(v.w,h3,l3);
    *(__nv_bfloat162*)&g_Zh[i]     = __nv_bfloat162(h0,h1);
    *(__nv_bfloat162*)&g_Zh[i + 2] = __nv_bfloat162(h2,h3);
    *(__nv_bfloat162*)&g_Zl[i]     = __nv_bfloat162(l0,l1);
    *(__nv_bfloat162*)&g_Zl[i + 2] = __nv_bfloat162(l2,l3);
}

// W_{q,k,v}[h][k][d] -> Wt[n = which*1024 + h*64 + d][k], split hi/lo.
__global__ __launch_bounds__(256) void split_wqkv(
    const float* __restrict__ Wq, const float* __restrict__ Wk, const float* __restrict__ Wv)
{
    __shared__ float sm[64][65];
    const int k0 = blockIdx.x * 64;
    const int n0 = blockIdx.y * 64;       // 0..3008
    const int which = n0 >> 10;
    const int h = (n0 >> 6) & 15;
    const float* __restrict__ W = (which == 0) ? Wq : (which == 1) ? Wk : Wv;
    const int t = threadIdx.x;

#pragma unroll
    for (int i = 0; i < 16; i++) {
        int idx = t + i * 256;
        int r = idx >> 6, c = idx & 63;
        sm[r][c] = W[h * (DD * DHD) + (k0 + r) * DHD + c];
    }
    __syncthreads();
#pragma unroll
    for (int i = 0; i < 16; i++) {
        int idx = t + i * 256;
        int nl = idx >> 6, kl = idx & 63;
        __nv_bfloat16 hi, lo;
        bsplit(sm[kl][nl], hi, lo);
        g_Wth[(n0 + nl) * DD + k0 + kl] = hi;
        g_Wtl[(n0 + nl) * DD + k0 + kl] = lo;
    }
}

// W_O flattened row-major [1024 k][1024 n] -> Wot[n][k], split hi/lo.
__global__ __launch_bounds__(256) void split_wo(const float* __restrict__ Wo)
{
    __shared__ float sm[64][65];
    const int k0 = blockIdx.x * 64;
    const int n0 = blockIdx.y * 64;
    const int t = threadIdx.x;

#pragma unroll
    for (int i = 0; i < 16; i++) {
        int idx = t + i * 256;
        int r = idx >> 6, c = idx & 63;
        sm[r][c] = Wo[(k0 + r) * DD + n0 + c];
    }
    __syncthreads();
#pragma unroll
    for (int i = 0; i < 16; i++) {
        int idx = t + i * 256;
        int nl = idx >> 6, kl = idx & 63;
        __nv_bfloat16 hi, lo;
        bsplit(sm[kl][nl], hi, lo);
        g_Woth[(n0 + nl) * DD + k0 + kl] = hi;
        g_Wotl[(n0 + nl) * DD + k0 + kl] = lo;
    }
}

__global__ __launch_bounds__(256) void bias_prep(
    const float* __restrict__ bq, const float* __restrict__ bk,
    const float* __restrict__ bv, const float* __restrict__ bo)
{
    int id = blockIdx.x * 256 + threadIdx.x;   // 0..4095
    if (id < NQKV) {
        int which = id >> 10, n = id & 1023;
        g_bias[id] = (which == 0) ? bq[n] : (which == 1) ? bk[n] : bv[n];
    } else {
        int n = id - NQKV;
        float s = 0.0f;
#pragma unroll
        for (int h = 0; h < HH; h++) s += bo[h * DD + n];
        g_bias[id] = s;
    }
}

// ---------------------------------------------------------------------------
// bf16x3 GEMM: C[m,n] = sum_k A[m,k]*B[n,k] + bias[n]   (K = 1024)
// A given as hi/lo bf16 [M][1024]; B as hi/lo bf16 [N][1024] (pre-transposed).
// Block 128x128, BK=32, 8 warps (2x4), warp tile 64x32. cp.async double buffer.
// Smem per array: [128][20 u32] (16 kpairs + 4 pad; stride 20 -> conflict-free
// ldmatrix: 8 consecutive rows hit banks {0,20,8,28,16,4,24,12}+c).
// ---------------------------------------------------------------------------
#define GSTG 10240                      // u32 per stage (4 arrays x 128*20)
#define GEMM_SMEM (2 * GSTG * 4)        // 81920 B

__global__ __launch_bounds__(256) void gemm_bf16x3(
    const __nv_bfloat16* __restrict__ Ah, const __nv_bfloat16* __restrict__ Al,
    const __nv_bfloat16* __restrict__ Bh, const __nv_bfloat16* __restrict__ Bl,
    const float* __restrict__ bias, float* __restrict__ C, int ldC)
{
    extern __shared__ __align__(16) uint32_t sm[];
    const uint32_t smb = smem_u32(sm);

    const int n0   = blockIdx.x * 128;
    const int m0   = blockIdx.y * 128;
    const int t    = threadIdx.x;
    const int lane = t & 31, w = t >> 5;
    const int g    = lane >> 2, tq = lane & 3;
    const int wm   = w & 1, wn = w >> 1;

    // ldmatrix per-lane address components
    const int a_row_l = ((lane >> 3) & 1) * 8 + (lane & 7);
    const int a_col_l = (lane >> 4) * 4;
    const int b_row_l = (lane >> 4) * 8 + (lane & 7);
    const int b_col_l = ((lane >> 3) & 1) * 4;

    // cp.async per-thread chunk decomposition (8 chunks of 16B per thread)
    // id = t + i*256 in [0,2048): which = id>>9 (0:Ah 1:Al 2:Bh 3:Bl),
    // r = (id>>2)&127, c = id&3  (chunk c covers k-halves c*8..c*8+7)
    const __nv_bfloat16* srcs[4] = { Ah + (size_t)m0 * DD, Al + (size_t)m0 * DD,
                                     Bh + (size_t)n0 * DD, Bl + (size_t)n0 * DD };

    float acc[4][4][4];
#pragma unroll
    for (int mt = 0; mt < 4; mt++)
#pragma unroll
        for (int nt = 0; nt < 4; nt++)
#pragma unroll
            for (int i = 0; i < 4; i++) acc[mt][nt][i] = 0.0f;

    // ---- prologue: load stage 0 (k0 = 0) ----
#pragma unroll
    for (int i = 0; i < 8; i++) {
        int id = t + i * 256;
        int which = id >> 9, r = (id >> 2) & 127, c = id & 3;
        const __nv_bfloat16* gp = srcs[which] + (size_t)r * DD + c * 8;
        uint32_t sa = smb + (which * 2560 + r * 20 + c * 4) * 4;
        asm volatile("cp.async.cg.shared.global [%0], [%1], 16;" :: "r"(sa), "l"(gp));
    }
    asm volatile("cp.async.commit_group;" ::: "memory");

    for (int kt = 0; kt < 32; kt++) {
        asm volatile("cp.async.wait_group 0;" ::: "memory");
        __syncthreads();

        if (kt + 1 < 32) {
            int k0n = (kt + 1) * 32;
            uint32_t stoff = ((kt + 1) & 1) * GSTG;
#pragma unroll
            for (int i = 0; i < 8; i++) {
                int id = t + i * 256;
                int which = id >> 9, r = (id >> 2) & 127, c = id & 3;
                const __nv_bfloat16* gp = srcs[which] + (size_t)r * DD + k0n + c * 8;
                uint32_t sa = smb + (stoff + which * 2560 + r * 20 + c * 4) * 4;
                asm volatile("cp.async.cg.shared.global [%0], [%1], 16;" :: "r"(sa), "l"(gp));
            }
            asm volatile("cp.async.commit_group;" ::: "memory");
        }

        // ---- compute on stage kt&1 ----
        const uint32_t st = (kt & 1) * GSTG;
#pragma unroll
        for (int kk = 0; kk < 2; kk++) {
            uint32_t ah[4][4], al[4][4], bh[2][4], bl[2][4];
#pragma unroll
            for (int mt = 0; mt < 4; mt++) {
                uint32_t off = (st + (wm * 64 + mt * 16 + a_row_l) * 20 + kk * 8 + a_col_l) * 4;
                ldm4(ah[mt], smb + off);                 // Ah at +0
                ldm4(al[mt], smb + off + 2560 * 4);      // Al at +2560 u32
            }
#pragma unroll
            for (int p = 0; p < 2; p++) {
                uint32_t off = (st + 5120 + (wn * 32 + p * 16 + b_row_l) * 20 + kk * 8 + b_col_l) * 4;
                ldm4(bh[p], smb + off);                  // Bh at +5120
                ldm4(bl[p], smb + off + 2560 * 4);       // Bl at +7680
            }
#pragma unroll
            for (int mt = 0; mt < 4; mt++)
#pragma unroll
                for (int nt = 0; nt < 4; nt++)
                    mma_bf16(acc[mt][nt], ah[mt], &bh[nt >> 1][(nt & 1) * 2]);
#pragma unroll
            for (int mt = 0; mt < 4; mt++)
#pragma unroll
                for (int nt = 0; nt < 4; nt++)
                    mma_bf16(acc[mt][nt], ah[mt], &bl[nt >> 1][(nt & 1) * 2]);
#pragma unroll
            for (int mt = 0; mt < 4; mt++)
#pragma unroll
                for (int nt = 0; nt < 4; nt++)
                    mma_bf16(acc[mt][nt], al[mt], &bh[nt >> 1][(nt & 1) * 2]);
        }
    }

    // ---- epilogue: bias + store ----
#pragma unroll
    for (int mt = 0; mt < 4; mt++) {
        int m = m0 + wm * 64 + mt * 16 + g;
#pragma unroll
        for (int nt = 0; nt < 4; nt++) {
            int n = n0 + wn * 32 + nt * 8 + 2 * tq;
            float b0 = bias[n], b1 = bias[n + 1];
            *(float2*)&C[(size_t)m * ldC + n] =
                make_float2(acc[mt][nt][0] + b0, acc[mt][nt][1] + b1);
            *(float2*)&C[(size_t)(m + 8) * ldC + n] =
                make_float2(acc[mt][nt][2] + b0, acc[mt][nt][3] + b1);
        }
    }
}

// ---------------------------------------------------------------------------
// Flash attention (causal), tf32 mma. 64x64 tiles, 4 warps (128 thr).
// Unchanged from round 6 except Q/K/V read from fused g_QKV (stride 3072).
// ---------------------------------------------------------------------------
#define KSTR 68
#define VSTR 72
#define FLASH_SMEM ((64*KSTR + 64*VSTR + 64*KSTR) * 4)   // 53248 B

__global__ __launch_bounds__(128) void flash_kernel()
{
    extern __shared__ __align__(16) uint32_t sm[];
    uint32_t* Ks = sm;
    uint32_t* Vs = sm + 64 * KSTR;
    uint32_t* Ps = sm + 64 * KSTR + 64 * VSTR;

    const int qt = blockIdx.x, h = blockIdx.y, b = blockIdx.z;
    const int t = threadIdx.x, lane = t & 31, w = t >> 5;
    const int g = lane >> 2, tq = lane & 3;
    const float scale = 0.125f;

    const int qoff = h * 64;            // Q columns in g_QKV
    const int koff = 1024 + h * 64;     // K columns
    const int voff = 2048 + h * 64;     // V columns

#pragma unroll
    for (int i = 0; i < 8; i++) {
        int idx = lane + i * 32;
        int r   = idx >> 4;
        int c4  = (idx & 15) * 4;
        float4 v = *(const float4*)&g_QKV[(size_t)(b * SS + qt * 64 + w * 16 + r) * NQKV + qoff + c4];
        *(uint4*)&Ps[(w * 16 + r) * KSTR + c4] =
            make_uint4(f2tf(v.x), f2tf(v.y), f2tf(v.z), f2tf(v.w));
    }
    __syncwarp();
    uint32_t qa[8][4];
#pragma unroll
    for (int kk = 0; kk < 8; kk++) {
        int rb = (w * 16 + g) * KSTR;
        qa[kk][0] = Ps[rb + kk * 8 + tq];
        qa[kk][1] = Ps[rb + 8 * KSTR + kk * 8 + tq];
        qa[kk][2] = Ps[rb + kk * 8 + tq + 4];
        qa[kk][3] = Ps[rb + 8 * KSTR + kk * 8 + tq + 4];
    }

    float m_i[2] = {-1e30f, -1e30f}, l_i[2] = {0.0f, 0.0f};
    float O[8][4];
#pragma unroll
    for (int nt = 0; nt < 8; nt++)
#pragma unroll
        for (int i = 0; i < 4; i++) O[nt][i] = 0.0f;

    for (int j = 0; j <= qt; j++) {
        __syncthreads();
#pragma unroll
        for (int i = 0; i < 8; i++) {
            int idx = t + i * 128;
            int r   = idx >> 4;
            int c4  = (idx & 15) * 4;
            size_t go = (size_t)(b * SS + j * 64 + r) * NQKV;
            float4 kv = *(const float4*)&g_QKV[go + koff + c4];
            float4 vv = *(const float4*)&g_QKV[go + voff + c4];
            *(uint4*)&Ks[r * KSTR + c4] = make_uint4(f2tf(kv.x), f2tf(kv.y), f2tf(kv.z), f2tf(kv.w));
            *(uint4*)&Vs[r * VSTR + c4] = make_uint4(f2tf(vv.x), f2tf(vv.y), f2tf(vv.z), f2tf(vv.w));
        }
        __syncthreads();

        float S[8][4];
#pragma unroll
        for (int nt = 0; nt < 8; nt++)
#pragma unroll
            for (int i = 0; i < 4; i++) S[nt][i] = 0.0f;

#pragma unroll
        for (int kk = 0; kk < 8; kk++) {
#pragma unroll
            for (int nt = 0; nt < 8; nt++) {
                uint32_t kb[2];
                kb[0] = Ks[(nt * 8 + g) * KSTR + kk * 8 + tq];
                kb[1] = Ks[(nt * 8 + g) * KSTR + kk * 8 + tq + 4];
                mma_tf32(S[nt], qa[kk], kb);
            }
        }

        if (j == qt) {
            int r0 = w * 16 + g, r1 = r0 + 8;
#pragma unroll
            for (int nt = 0; nt < 8; nt++) {
                int c = nt * 8 + 2 * tq;
                S[nt][0] = (c     <= r0) ? S[nt][0] * scale : -1e30f;
                S[nt][1] = (c + 1 <= r0) ? S[nt][1] * scale : -1e30f;
                S[nt][2] = (c     <= r1) ? S[nt][2] * scale : -1e30f;
                S[nt][3] = (c + 1 <= r1) ? S[nt][3] * scale : -1e30f;
            }
        } else {
#pragma unroll
            for (int nt = 0; nt < 8; nt++)
#pragma unroll
                for (int i = 0; i < 4; i++) S[nt][i] *= scale;
        }

        float mx0 = -1e30f, mx1 = -1e30f;
#pragma unroll
        for (int nt = 0; nt < 8; nt++) {
            mx0 = fmaxf(mx0, fmaxf(S[nt][0], S[nt][1]));
            mx1 = fmaxf(mx1, fmaxf(S[nt][2], S[nt][3]));
        }
        mx0 = fmaxf(mx0, __shfl_xor_sync(0xffffffffu, mx0, 1));
        mx0 = fmaxf(mx0, __shfl_xor_sync(0xffffffffu, mx0, 2));
        mx1 = fmaxf(mx1, __shfl_xor_sync(0xffffffffu, mx1, 1));
        mx1 = fmaxf(mx1, __shfl_xor_sync(0xffffffffu, mx1, 2));

        float mn0 = fmaxf(m_i[0], mx0), mn1 = fmaxf(m_i[1], mx1);
        float c0 = __expf(m_i[0] - mn0), c1 = __expf(m_i[1] - mn1);
        m_i[0] = mn0; m_i[1] = mn1;

        float rs0 = 0.0f, rs1 = 0.0f;
#pragma unroll
        for (int nt = 0; nt < 8; nt++) {
            float p0 = __expf(S[nt][0] - mn0);
            float p1 = __expf(S[nt][1] - mn0);
            float p2 = __expf(S[nt][2] - mn1);
            float p3 = __expf(S[nt][3] - mn1);
            rs0 += p0 + p1; rs1 += p2 + p3;
            int cb = nt * 8 + 2 * tq;
            *(uint2*)&Ps[(w * 16 + g) * KSTR + cb]     = make_uint2(f2tf(p0), f2tf(p1));
            *(uint2*)&Ps[(w * 16 + g + 8) * KSTR + cb] = make_uint2(f2tf(p2), f2tf(p3));
        }
        rs0 += __shfl_xor_sync(0xffffffffu, rs0, 1);
        rs0 += __shfl_xor_sync(0xffffffffu, rs0, 2);
        rs1 += __shfl_xor_sync(0xffffffffu, rs1, 1);
        rs1 += __shfl_xor_sync(0xffffffffu, rs1, 2);

        l_i[0] = l_i[0] * c0 + rs0;
        l_i[1] = l_i[1] * c1 + rs1;
#pragma unroll
        for (int nt = 0; nt < 8; nt++) {
            O[nt][0] *= c0; O[nt][1] *= c0;
            O[nt][2] *= c1; O[nt][3] *= c1;
        }
        __syncwarp();

#pragma unroll
        for (int kk = 0; kk < 8; kk++) {
            uint32_t pa[4];
            int rb = (w * 16 + g) * KSTR + kk * 8;
            pa[0] = Ps[rb + tq];
            pa[1] = Ps[rb + 8 * KSTR + tq];
            pa[2] = Ps[rb + tq + 4];
            pa[3] = Ps[rb + 8 * KSTR + tq + 4];
#pragma unroll
            for (int nt = 0; nt < 8; nt++) {
                uint32_t vb[2];
                vb[0] = Vs[(kk * 8 + tq) * VSTR + nt * 8 + g];
                vb[1] = Vs[(kk * 8 + tq + 4) * VSTR + nt * 8 + g];
                mma_tf32(O[nt], pa, vb);
            }
        }
    }

    float inv0 = 1.0f / l_i[0], inv1 = 1.0f / l_i[1];
    int m = b * SS + qt * 64 + w * 16 + g;
#pragma unroll
    for (int nt = 0; nt < 8; nt++) {
        int c = h * 64 + nt * 8 + 2 * tq;
        *(float2*)&g_Z[(size_t)m * DD + c]       = make_float2(O[nt][0] * inv0, O[nt][1] * inv0);
        *(float2*)&g_Z[(size_t)(m + 8) * DD + c] = make_float2(O[nt][2] * inv1, O[nt][3] * inv1);
    }
}

// ---------------------------------------------------------------------------
extern "C" void kernel_launch(void* const* d_in, const int* in_sizes, int n_in,
                              void* d_out, int out_size)
{
    (void)in_sizes; (void)n_in; (void)out_size;
    const float* x  = (const float*)d_in[0];
    const float* Wq = (const float*)d_in[1];
    const float* bq = (const float*)d_in[2];
    const float* Wk = (const float*)d_in[3];
    const float* bk = (const float*)d_in[4];
    const float* Wv = (const float*)d_in[5];
    const float* Wo = (const float*)d_in[6];
    const float* bv = (const float*)d_in[7];
    const float* bo = (const float*)d_in[8];
    float* out = (float*)d_out;

    cudaFuncSetAttribute(flash_kernel,
                         cudaFuncAttributeMaxDynamicSharedMemorySize, FLASH_SMEM);
    cudaFuncSetAttribute(gemm_bf16x3,
                         cudaFuncAttributeMaxDynamicSharedMemorySize, GEMM_SMEM);

    __nv_bfloat16 *Xh, *Xl, *Wth, *Wtl, *Zh, *Zl, *Woth, *Wotl;
    float *bias_d, *qkv_d;
    cudaGetSymbolAddress((void**)&Xh,   g_Xh);
    cudaGetSymbolAddress((void**)&Xl,   g_Xl);
    cudaGetSymbolAddress((void**)&Wth,  g_Wth);
    cudaGetSymbolAddress((void**)&Wtl,  g_Wtl);
    cudaGetSymbolAddress((void**)&Zh,   g_Zh);
    cudaGetSymbolAddress((void**)&Zl,   g_Zl);
    cudaGetSymbolAddress((void**)&Woth, g_Woth);
    cudaGetSymbolAddress((void**)&Wotl, g_Wotl);
    cudaGetSymbolAddress((void**)&bias_d, g_bias);
    cudaGetSymbolAddress((void**)&qkv_d,  g_QKV);

    // pre-passes
    split_ext<<<MM*DD/1024, 256>>>(x, Xh, Xl);
    split_wqkv<<<dim3(16, 48), 256>>>(Wq, Wk, Wv);
    split_wo<<<dim3(16, 16), 256>>>(Wo);
    bias_prep<<<16, 256>>>(bq, bk, bv, bo);

    // QKV projection
    gemm_bf16x3<<<dim3(24, 32), 256, GEMM_SMEM>>>(Xh, Xl, Wth, Wtl, bias_d, qkv_d, NQKV);
    // attention
    flash_kernel<<<dim3(32, HH, BB), 128, FLASH_SMEM>>>();
    // output projection
    split_z<<<MM*DD/1024, 256>>>();
    gemm_bf16x3<<<dim3(8, 32), 256, GEMM_SMEM>>>(Zh, Zl, Woth, Wotl, bias_d + NQKV, out, DD);
}